// round 11
// baseline (speedup 1.0000x reference)
#include <cuda_runtime.h>
#include <cstdint>
#include <cstddef>

namespace {

constexpr int kB  = 4;
constexpr int kH  = 8;
constexpr int kL  = 2048;
constexpr int kR  = 8;
constexpr int kDV = 128;

constexpr int TM = 32;           // rows per CTA (small -> 3 CTAs/SM)
constexpr int KT = 32;           // K-tile
constexpr int NT = 256;          // threads
constexpr int NTILES = kL / KT;  // 64

constexpr int PSTRIDE = 36;      // p row stride (u32): A-frag conflict-free
constexpr int VSTRIDE = 136;     // v row stride (u32): B-frag conflict-free
constexpr float kLog2e = 1.44269504088896340736f;

__device__ __forceinline__ uint32_t f2tf32(float x) {
    uint32_t r; asm("cvt.rna.tf32.f32 %0, %1;" : "=r"(r) : "f"(x)); return r;
}
__device__ __forceinline__ float ex2(float x) {
    float r; asm("ex2.approx.f32 %0, %1;" : "=f"(r) : "f"(x)); return r;
}
__device__ __forceinline__ void mma_tf32(float d[4], const uint32_t a[4],
                                         uint32_t b0, uint32_t b1) {
    asm volatile(
        "mma.sync.aligned.m16n8k8.row.col.f32.tf32.tf32.f32 "
        "{%0,%1,%2,%3}, {%4,%5,%6,%7}, {%8,%9}, {%0,%1,%2,%3};"
        : "+f"(d[0]), "+f"(d[1]), "+f"(d[2]), "+f"(d[3])
        : "r"(a[0]), "r"(a[1]), "r"(a[2]), "r"(a[3]), "r"(b0), "r"(b1));
}
__device__ __forceinline__ uint32_t smem_u32(const void* p) {
    uint32_t a;
    asm("{ .reg .u64 t; cvta.to.shared.u64 t, %1; cvt.u32.u64 %0, t; }"
        : "=r"(a) : "l"(p));
    return a;
}
__device__ __forceinline__ void cp16(uint32_t saddr, const void* g) {
    asm volatile("cp.async.ca.shared.global [%0], [%1], 16;"
                 :: "r"(saddr), "l"(g) : "memory");
}
__device__ __forceinline__ void cp_commit() {
    asm volatile("cp.async.commit_group;" ::: "memory");
}
__device__ __forceinline__ void cp_wait1() {
    asm volatile("cp.async.wait_group 1;" ::: "memory");
}

struct __align__(16) SmemLayout {
    uint32_t p[2][TM][PSTRIDE];    // 9.2 KB  (tf32 E tiles, double buffered)
    uint32_t v[3][KT][VSTRIDE];    // 52.2 KB (raw f32 v tiles, cp.async ring)
    float    a2t[2][kR][KT];       // 2 KB    (streamed a2 K-tiles)
    float    inv[TM];              // 128 B
};
// ~63.6 KB -> 3 CTAs/SM

__global__ void __launch_bounds__(NT, 3)
fra_kernel(const float* __restrict__ gv,
           const float* __restrict__ ga1,
           const float* __restrict__ ga2,
           const int*   __restrict__ gmask,
           float* __restrict__ gout,
           float* __restrict__ gattn)
{
    extern __shared__ char smem_raw[];
    SmemLayout& S = *reinterpret_cast<SmemLayout*>(smem_raw);

    const int h    = blockIdx.x;   // heads fastest: 8 heads share mask tile in L2
    const int tile = blockIdx.y;
    const int b    = blockIdx.z;
    const int bh   = b * kH + h;
    const int i0g  = tile * TM;
    const int t    = threadIdx.x;
    const int w    = t >> 5;
    const int l    = t & 31;

    const float* a2base = ga2 + (size_t)bh * kR * kL;
    const float* a1base = ga1 + ((size_t)bh * kL + i0g) * kR;
    const float* vbase  = gv  + (size_t)bh * kL * kDV;
    const int*   mbase  = gmask + ((size_t)b * kL + i0g) * kL;
    float* attnbase = gattn + ((size_t)bh * kL + i0g) * kL;
    float* outbase  = gout  + ((size_t)bh * kL + i0g) * kDV;

    // score mapping: 1 row per thread group: row rp, cols cg*4 within K-tile
    const int rp = t >> 3;   // 0..31
    const int cg = t & 7;    // 0..7

    // a1 (pre-scaled by log2e) for this thread's row
    float a1r[kR];
    {
        const float4* src = (const float4*)(a1base + (size_t)rp * kR);
        float4 q0 = src[0], q1 = src[1];
        a1r[0] = q0.x * kLog2e; a1r[1] = q0.y * kLog2e;
        a1r[2] = q0.z * kLog2e; a1r[3] = q0.w * kLog2e;
        a1r[4] = q1.x * kLog2e; a1r[5] = q1.y * kLog2e;
        a1r[6] = q1.z * kLog2e; a1r[7] = q1.w * kLog2e;
    }

    // GEMM warp grid 2x4 (wm x wn); warp tile 16 rows x 32 cols
    const int wm  = w >> 2;
    const int wn  = w & 3;
    const int qid = l >> 2;
    const int tig = l & 3;

    float acc[4][4];
    #pragma unroll
    for (int nt = 0; nt < 4; ++nt)
        #pragma unroll
        for (int e = 0; e < 4; ++e) acc[nt][e] = 0.f;

    float rs = 0.f;

    // ---- cp.async v addressing ----
    const uint32_t vs_base = smem_u32(&S.v[0][0][0]);
    const uint32_t voff0 = (uint32_t)((w * VSTRIDE + 4 * l) * 4);
    const float* vg0 = vbase + (size_t)w * kDV + 4 * l;
    constexpr uint32_t VROW8 = (uint32_t)(8 * VSTRIDE * 4);
    constexpr size_t   VG8   = (size_t)8 * kDV;
    constexpr uint32_t VSLOT = KT * VSTRIDE * 4;
    constexpr size_t   VGT   = (size_t)KT * kDV;

    // ---- prologue ----
    #pragma unroll
    for (int k = 0; k < 4; ++k)
        cp16(vs_base + voff0 + k * VROW8, vg0 + k * VG8);
    cp_commit();

    const int ar = t >> 3;   // only t<64 stage a2
    const int ac = t & 7;
    if (t < 64)
        *(float4*)&S.a2t[0][ar][ac * 4] =
            *(const float4*)(a2base + (size_t)ar * kL + ac * 4);

    int4 mq_buf[2];
    mq_buf[0] = *(const int4*)(mbase + (size_t)rp * kL + 0 * KT + cg * 4);
    mq_buf[1] = *(const int4*)(mbase + (size_t)rp * kL + 1 * KT + cg * 4);
    __syncthreads();

    // ============ fused sweep: e = mask*exp2(s); attn STG (unnorm); E@V MMA ============
    int vcur = 0, vnxt = 1;
    #pragma unroll 2
    for (int jt = 0; jt < NTILES; ++jt) {
        const int buf = jt & 1;
        const int j0  = jt * KT;

        // ---- issue cp.async for v tile jt+1 ----
        {
            const size_t goff = (jt + 1 < NTILES) ? (size_t)(jt + 1) * VGT : 0;
            const uint32_t sb = vs_base + (uint32_t)vnxt * VSLOT + voff0;
            #pragma unroll
            for (int k = 0; k < 4; ++k)
                cp16(sb + k * VROW8, vg0 + goff + k * VG8);
            cp_commit();
        }

        // ---- prefetch next a2 tile ----
        float4 a2n;
        const int jn = (jt + 1 < NTILES) ? j0 + KT : 0;
        if (t < 64)
            a2n = *(const float4*)(a2base + (size_t)ar * kL + jn + ac * 4);

        // ---- scores: 1 row x 4 cols, scalar FFMA ----
        float s0 = 0.f, s1 = 0.f, s2 = 0.f, s3 = 0.f;
        #pragma unroll
        for (int r = 0; r < kR; ++r) {
            float4 q = *(const float4*)&S.a2t[buf][r][cg * 4];
            const float a = a1r[r];
            s0 = fmaf(a, q.x, s0);
            s1 = fmaf(a, q.y, s1);
            s2 = fmaf(a, q.z, s2);
            s3 = fmaf(a, q.w, s3);
        }

        // ---- e = mask*exp2(s): attn STG (unnormalized), rowsum, p STS (tf32) ----
        {
            const int4 m = mq_buf[buf];
            float4 e;
            e.x = m.x ? ex2(s0) : 0.f;
            e.y = m.y ? ex2(s1) : 0.f;
            e.z = m.z ? ex2(s2) : 0.f;
            e.w = m.w ? ex2(s3) : 0.f;
            rs += (e.x + e.y) + (e.z + e.w);
            *(float4*)(attnbase + (size_t)rp * kL + j0 + cg * 4) = e;
            uint4 u;
            u.x = f2tf32(e.x); u.y = f2tf32(e.y);
            u.z = f2tf32(e.z); u.w = f2tf32(e.w);
            *(uint4*)&S.p[buf][rp][cg * 4] = u;
        }

        // ---- mask prefetch 2 tiles ahead ----
        {
            const int jm = (jt + 2 < NTILES) ? (jt + 2) * KT : 0;
            mq_buf[buf] = *(const int4*)(mbase + (size_t)rp * kL + jm + cg * 4);
        }

        // ---- stage next a2 tile ----
        if (t < 64)
            *(float4*)&S.a2t[buf ^ 1][ar][ac * 4] = a2n;

        cp_wait1();        // v tile jt resident
        __syncthreads();   // publish p/a2/v(jt)

        // ---- HMMA: D[16*wm.., 32*wn..] += E * V  (V raw f32 -> tf32 truncation) ----
        const uint32_t* vt = &S.v[vcur][0][0];
        const uint32_t* pr = &S.p[buf][16 * wm][0];
        #pragma unroll
        for (int s = 0; s < 4; ++s) {
            const int k0 = 8 * s + tig;
            uint32_t a[4];
            a[0] = pr[(size_t)qid * PSTRIDE + k0];
            a[1] = pr[(size_t)(qid + 8) * PSTRIDE + k0];
            a[2] = pr[(size_t)qid * PSTRIDE + k0 + 4];
            a[3] = pr[(size_t)(qid + 8) * PSTRIDE + k0 + 4];
            #pragma unroll
            for (int nt = 0; nt < 4; ++nt) {
                const int n = 32 * wn + 8 * nt + qid;
                uint32_t b0 = vt[(size_t)(8 * s + tig) * VSTRIDE + n];
                uint32_t b1 = vt[(size_t)(8 * s + 4 + tig) * VSTRIDE + n];
                mma_tf32(acc[nt], a, b0, b1);
            }
        }

        vcur = vnxt;
        vnxt = (vnxt == 2) ? 0 : vnxt + 1;
    }

    // ---- rowsum reduce over 8 cg lanes (warp-local) ----
    float invr;
    {
        float r = rs;
        r += __shfl_xor_sync(0xffffffffu, r, 1);
        r += __shfl_xor_sync(0xffffffffu, r, 2);
        r += __shfl_xor_sync(0xffffffffu, r, 4);
        invr = 1.0f / r;
        if (cg == 0) S.inv[rp] = invr;
    }
    __syncthreads();

    // ---- out epilogue: scale accumulators by row inv ----
    {
        const int row0 = 16 * wm + qid;
        const float ivlo = S.inv[row0];
        const float ivhi = S.inv[row0 + 8];
        #pragma unroll
        for (int nt = 0; nt < 4; ++nt) {
            const int col = 32 * wn + 8 * nt + 2 * tig;
            float2 lo; lo.x = acc[nt][0] * ivlo; lo.y = acc[nt][1] * ivlo;
            float2 hi; hi.x = acc[nt][2] * ivhi; hi.y = acc[nt][3] * ivhi;
            *(float2*)(outbase + (size_t)row0 * kDV + col)       = lo;
            *(float2*)(outbase + (size_t)(row0 + 8) * kDV + col) = hi;
        }
    }

    // ---- attn rescale: each thread rescales exactly the float4s it wrote ----
    {
        float* aprow = attnbase + (size_t)rp * kL + cg * 4;
        #pragma unroll 8
        for (int jt = 0; jt < NTILES; ++jt) {
            float4 e = *(const float4*)(aprow + jt * KT);
            e.x *= invr; e.y *= invr; e.z *= invr; e.w *= invr;
            *(float4*)(aprow + jt * KT) = e;
        }
    }
}

} // namespace

extern "C" void kernel_launch(void* const* d_in, const int* in_sizes, int n_in,
                              void* d_out, int out_size) {
    const float* v    = (const float*)d_in[0];
    const float* a1   = (const float*)d_in[1];
    const float* a2   = (const float*)d_in[2];
    const int*   mask = (const int*)d_in[3];

    float* out  = (float*)d_out;
    float* attn = out + (size_t)kB * kH * kL * kDV;

    const int smem = (int)sizeof(SmemLayout);
    cudaFuncSetAttribute(fra_kernel, cudaFuncAttributeMaxDynamicSharedMemorySize, smem);

    dim3 grid(kH, kL / TM, kB);   // heads fastest -> mask tile L2 reuse across 8 heads
    fra_kernel<<<grid, NT, smem>>>(v, a1, a2, mask, out, attn);
}

// round 12
// speedup vs baseline: 1.1373x; 1.1373x over previous
#include <cuda_runtime.h>
#include <cstdint>
#include <cstddef>

namespace {

constexpr int kB  = 4;
constexpr int kH  = 8;
constexpr int kL  = 2048;
constexpr int kR  = 8;
constexpr int kDV = 128;

constexpr int TM = 64;           // rows per CTA
constexpr int KT = 32;           // K-tile
constexpr int NT = 256;          // threads
constexpr int NTILES = kL / KT;  // 64

constexpr int PSTRIDE = 36;      // p row stride (u32): ldmatrix rows hit distinct 16B groups
constexpr int VSTRIDE = 136;     // v row stride (u32): B-frag conflict-free
constexpr float kLog2e = 1.44269504088896340736f;

typedef unsigned long long ull;

__device__ __forceinline__ ull dup2(float x) {
    ull r; asm("mov.b64 %0, {%1,%1};" : "=l"(r) : "f"(x)); return r;
}
__device__ __forceinline__ void unpack2(ull v, float& lo, float& hi) {
    asm("mov.b64 {%0,%1}, %2;" : "=f"(lo), "=f"(hi) : "l"(v));
}
__device__ __forceinline__ ull fma2(ull a, ull b, ull c) {
    ull d; asm("fma.rn.f32x2 %0, %1, %2, %3;" : "=l"(d) : "l"(a), "l"(b), "l"(c));
    return d;
}
__device__ __forceinline__ uint32_t f2tf32(float x) {
    uint32_t r; asm("cvt.rna.tf32.f32 %0, %1;" : "=r"(r) : "f"(x)); return r;
}
__device__ __forceinline__ float ex2(float x) {
    float r; asm("ex2.approx.f32 %0, %1;" : "=f"(r) : "f"(x)); return r;
}
__device__ __forceinline__ void mma_tf32(float d[4], const uint32_t a[4],
                                         uint32_t b0, uint32_t b1) {
    asm volatile(
        "mma.sync.aligned.m16n8k8.row.col.f32.tf32.tf32.f32 "
        "{%0,%1,%2,%3}, {%4,%5,%6,%7}, {%8,%9}, {%0,%1,%2,%3};"
        : "+f"(d[0]), "+f"(d[1]), "+f"(d[2]), "+f"(d[3])
        : "r"(a[0]), "r"(a[1]), "r"(a[2]), "r"(a[3]), "r"(b0), "r"(b1));
}
__device__ __forceinline__ void ldmatrix_x4(uint32_t a[4], uint32_t addr) {
    asm volatile(
        "ldmatrix.sync.aligned.m8n8.x4.shared.b16 {%0,%1,%2,%3}, [%4];"
        : "=r"(a[0]), "=r"(a[1]), "=r"(a[2]), "=r"(a[3]) : "r"(addr));
}
__device__ __forceinline__ uint32_t smem_u32(const void* p) {
    uint32_t a;
    asm("{ .reg .u64 t; cvta.to.shared.u64 t, %1; cvt.u32.u64 %0, t; }"
        : "=r"(a) : "l"(p));
    return a;
}
__device__ __forceinline__ void cp16(uint32_t saddr, const void* g) {
    asm volatile("cp.async.ca.shared.global [%0], [%1], 16;"
                 :: "r"(saddr), "l"(g) : "memory");
}
__device__ __forceinline__ void cp_commit() {
    asm volatile("cp.async.commit_group;" ::: "memory");
}
__device__ __forceinline__ void cp_wait1() {
    asm volatile("cp.async.wait_group 1;" ::: "memory");
}

struct __align__(16) SmemLayout {
    uint32_t p[2][TM][PSTRIDE];    // 18.4 KB (tf32 E tiles, double buffered)
    uint32_t v[3][KT][VSTRIDE];    // 52.2 KB (raw f32 v tiles, cp.async ring)
    float    a2t[2][kR][KT];       // 2 KB   (streamed a2 K-tiles)
    float    inv[TM];              // 256 B
};
// ~73 KB -> 2 CTAs/SM

__global__ void __launch_bounds__(NT, 2)
fra_kernel(const float* __restrict__ gv,
           const float* __restrict__ ga1,
           const float* __restrict__ ga2,
           const int*   __restrict__ gmask,
           float* __restrict__ gout,
           float* __restrict__ gattn)
{
    extern __shared__ char smem_raw[];
    SmemLayout& S = *reinterpret_cast<SmemLayout*>(smem_raw);

    const int h    = blockIdx.x;   // heads fastest: 8 heads share mask tile in L2
    const int tile = blockIdx.y;
    const int b    = blockIdx.z;
    const int bh   = b * kH + h;
    const int i0g  = tile * TM;
    const int t    = threadIdx.x;
    const int w    = t >> 5;
    const int l    = t & 31;

    const float* a2base = ga2 + (size_t)bh * kR * kL;
    const float* a1base = ga1 + ((size_t)bh * kL + i0g) * kR;
    const float* vbase  = gv  + (size_t)bh * kL * kDV;
    const int*   mbase  = gmask + ((size_t)b * kL + i0g) * kL;
    float* attnbase = gattn + ((size_t)bh * kL + i0g) * kL;
    float* outbase  = gout  + ((size_t)bh * kL + i0g) * kDV;

    // score mapping: rows 2*rp+i (i=0,1), cols cg*4 within K-tile
    const int rp = t >> 3;   // 0..31
    const int cg = t & 7;    // 0..7

    // a1 (pre-scaled by log2e for ex2) for this thread's 2 rows
    float a1r[2][kR];
    #pragma unroll
    for (int i = 0; i < 2; ++i) {
        const float4* src = (const float4*)(a1base + (size_t)(rp * 2 + i) * kR);
        float4 q0 = src[0], q1 = src[1];
        a1r[i][0] = q0.x * kLog2e; a1r[i][1] = q0.y * kLog2e;
        a1r[i][2] = q0.z * kLog2e; a1r[i][3] = q0.w * kLog2e;
        a1r[i][4] = q1.x * kLog2e; a1r[i][5] = q1.y * kLog2e;
        a1r[i][6] = q1.z * kLog2e; a1r[i][7] = q1.w * kLog2e;
    }

    // GEMM warp grid 2x4 (wm x wn); warp tile 32 rows x 32 cols
    const int wm  = w >> 2;
    const int wn  = w & 3;
    const int qid = l >> 2;
    const int tig = l & 3;

    // ldmatrix A lane address: tile group g = l>>3
    //  g0: rows +0..7  cols k0    | g1: rows +8..15 cols k0
    //  g2: rows +0..7  cols k0+4  | g3: rows +8..15 cols k0+4
    const int lrow = 32 * wm + ((l >> 3) & 1) * 8 + (l & 7);
    const int lcol = ((l >> 4) & 1) * 4;
    uint32_t paddr[2];
    paddr[0] = smem_u32(&S.p[0][lrow][lcol]);
    paddr[1] = smem_u32(&S.p[1][lrow][lcol]);

    float acc[2][4][4];
    #pragma unroll
    for (int mt = 0; mt < 2; ++mt)
        #pragma unroll
        for (int nt = 0; nt < 4; ++nt)
            #pragma unroll
            for (int e = 0; e < 4; ++e) acc[mt][nt][e] = 0.f;

    float rs[2] = {0.f, 0.f};

    // ---- cp.async v addressing ----
    const uint32_t vs_base = smem_u32(&S.v[0][0][0]);
    uint32_t voff[4];
    #pragma unroll
    for (int k = 0; k < 4; ++k)
        voff[k] = (uint32_t)(((w + 8 * k) * VSTRIDE + 4 * l) * 4);
    const float* vg[4];
    #pragma unroll
    for (int k = 0; k < 4; ++k)
        vg[k] = vbase + (size_t)(w + 8 * k) * kDV + 4 * l;
    constexpr uint32_t VSLOT = KT * VSTRIDE * 4;
    constexpr size_t   VGT   = (size_t)KT * kDV;

    // ---- prologue ----
    #pragma unroll
    for (int k = 0; k < 4; ++k) cp16(vs_base + voff[k], vg[k]);
    cp_commit();

    const int ar = t >> 3;
    const int ac = t & 7;
    if (t < 64)
        *(float4*)&S.a2t[0][ar][ac * 4] =
            *(const float4*)(a2base + (size_t)ar * kL + ac * 4);

    int4 mq_buf[2][2];
    #pragma unroll
    for (int i = 0; i < 2; ++i) {
        mq_buf[0][i] = *(const int4*)(mbase + (size_t)(rp * 2 + i) * kL + 0 * KT + cg * 4);
        mq_buf[1][i] = *(const int4*)(mbase + (size_t)(rp * 2 + i) * kL + 1 * KT + cg * 4);
    }
    __syncthreads();

    // ================= fused sweep: e = mask*exp2(s); attn STG; E@V MMA =================
    int vcur = 0, vnxt = 1;
    #pragma unroll 2
    for (int jt = 0; jt < NTILES; ++jt) {
        const int buf = jt & 1;
        const int j0  = jt * KT;

        // ---- issue cp.async for v tile jt+1 into slot vnxt ----
        {
            const size_t goff = (jt + 1 < NTILES) ? (size_t)(jt + 1) * VGT : 0;
            const uint32_t sb = vs_base + (uint32_t)vnxt * VSLOT;
            #pragma unroll
            for (int k = 0; k < 4; ++k) cp16(sb + voff[k], vg[k] + goff);
            cp_commit();
        }

        // ---- prefetch next a2 tile ----
        float4 a2n;
        const int jn = (jt + 1 < NTILES) ? j0 + KT : 0;
        if (t < 64)
            a2n = *(const float4*)(a2base + (size_t)ar * kL + jn + ac * 4);

        // ---- scores: 2 rows x 4 cols (f32x2) from smem a2 tile ----
        ull sac[2][2];
        sac[0][0] = 0ULL; sac[0][1] = 0ULL;
        sac[1][0] = 0ULL; sac[1][1] = 0ULL;
        #pragma unroll
        for (int r = 0; r < kR; ++r) {
            ulonglong2 q = *(const ulonglong2*)&S.a2t[buf][r][cg * 4];
            #pragma unroll
            for (int i = 0; i < 2; ++i) {
                ull ad = dup2(a1r[i][r]);
                sac[i][0] = fma2(ad, q.x, sac[i][0]);
                sac[i][1] = fma2(ad, q.y, sac[i][1]);
            }
        }

        // ---- e = mask*exp2(s~): attn STG (unnormalized), rowsum, p STS (tf32) ----
        #pragma unroll
        for (int i = 0; i < 2; ++i) {
            const int row = rp * 2 + i;
            const int4 m = mq_buf[buf][i];
            float e0, e1, e2, e3;
            unpack2(sac[i][0], e0, e1);
            unpack2(sac[i][1], e2, e3);
            float4 e;
            e.x = m.x ? ex2(e0) : 0.f;
            e.y = m.y ? ex2(e1) : 0.f;
            e.z = m.z ? ex2(e2) : 0.f;
            e.w = m.w ? ex2(e3) : 0.f;
            rs[i] += (e.x + e.y) + (e.z + e.w);
            *(float4*)(attnbase + (size_t)row * kL + j0 + cg * 4) = e;
            uint4 u;
            u.x = f2tf32(e.x); u.y = f2tf32(e.y);
            u.z = f2tf32(e.z); u.w = f2tf32(e.w);
            *(uint4*)&S.p[buf][row][cg * 4] = u;
        }

        // ---- mask prefetch 2 tiles ahead (into the parity slot just consumed) ----
        {
            const int jm = (jt + 2 < NTILES) ? (jt + 2) * KT : 0;
            #pragma unroll
            for (int i = 0; i < 2; ++i)
                mq_buf[buf][i] =
                    *(const int4*)(mbase + (size_t)(rp * 2 + i) * kL + jm + cg * 4);
        }

        // ---- stage next a2 tile into the other buffer ----
        if (t < 64)
            *(float4*)&S.a2t[buf ^ 1][ar][ac * 4] = a2n;

        cp_wait1();        // v tile jt resident
        __syncthreads();   // publish p/a2/v(jt)

        // ---- HMMA: D[32*wm.., 32*wn..] += E * V  (A via ldmatrix; V raw f32) ----
        const uint32_t* vt = &S.v[vcur][0][0];
        const uint32_t ab = paddr[buf];
        #pragma unroll
        for (int s = 0; s < 4; ++s) {
            uint32_t a[2][4];
            ldmatrix_x4(a[0], ab + (uint32_t)(s * 32));
            ldmatrix_x4(a[1], ab + (uint32_t)(16 * PSTRIDE * 4 + s * 32));
            #pragma unroll
            for (int nt = 0; nt < 4; ++nt) {
                const int n = 32 * wn + 8 * nt + qid;
                uint32_t b0 = vt[(size_t)(8 * s + tig) * VSTRIDE + n];
                uint32_t b1 = vt[(size_t)(8 * s + 4 + tig) * VSTRIDE + n];
                mma_tf32(acc[0][nt], a[0], b0, b1);
                mma_tf32(acc[1][nt], a[1], b0, b1);
            }
        }

        vcur = vnxt;
        vnxt = (vnxt == 2) ? 0 : vnxt + 1;
    }

    // ---- rowsum reduce over 8 cg lanes (warp-local) ----
    float invr[2];
    #pragma unroll
    for (int i = 0; i < 2; ++i) {
        float r = rs[i];
        r += __shfl_xor_sync(0xffffffffu, r, 1);
        r += __shfl_xor_sync(0xffffffffu, r, 2);
        r += __shfl_xor_sync(0xffffffffu, r, 4);
        invr[i] = 1.0f / r;
        if (cg == 0) S.inv[rp * 2 + i] = invr[i];
    }
    __syncthreads();

    // ---- out epilogue: scale accumulators by row inv ----
    #pragma unroll
    for (int mt = 0; mt < 2; ++mt) {
        const int row0 = 32 * wm + 16 * mt + qid;
        const float ivlo = S.inv[row0];
        const float ivhi = S.inv[row0 + 8];
        #pragma unroll
        for (int nt = 0; nt < 4; ++nt) {
            const int col = 32 * wn + 8 * nt + 2 * tig;
            float2 lo; lo.x = acc[mt][nt][0] * ivlo; lo.y = acc[mt][nt][1] * ivlo;
            float2 hi; hi.x = acc[mt][nt][2] * ivhi; hi.y = acc[mt][nt][3] * ivhi;
            *(float2*)(outbase + (size_t)row0 * kDV + col)       = lo;
            *(float2*)(outbase + (size_t)(row0 + 8) * kDV + col) = hi;
        }
    }

    // ---- attn rescale: each thread rescales exactly the float4s it wrote ----
    #pragma unroll
    for (int i = 0; i < 2; ++i) {
        float* aprow = attnbase + (size_t)(rp * 2 + i) * kL + cg * 4;
        const float iv = invr[i];
        #pragma unroll 8
        for (int jt = 0; jt < NTILES; ++jt) {
            float4 e = *(const float4*)(aprow + jt * KT);
            e.x *= iv; e.y *= iv; e.z *= iv; e.w *= iv;
            *(float4*)(aprow + jt * KT) = e;
        }
    }
}

} // namespace

extern "C" void kernel_launch(void* const* d_in, const int* in_sizes, int n_in,
                              void* d_out, int out_size) {
    const float* v    = (const float*)d_in[0];
    const float* a1   = (const float*)d_in[1];
    const float* a2   = (const float*)d_in[2];
    const int*   mask = (const int*)d_in[3];

    float* out  = (float*)d_out;
    float* attn = out + (size_t)kB * kH * kL * kDV;

    const int smem = (int)sizeof(SmemLayout);
    cudaFuncSetAttribute(fra_kernel, cudaFuncAttributeMaxDynamicSharedMemorySize, smem);

    dim3 grid(kH, kL / TM, kB);   // heads fastest -> mask tile L2 reuse across 8 heads
    fra_kernel<<<grid, NT, smem>>>(v, a1, a2, mask, out, attn);
}

// round 13
// speedup vs baseline: 1.3711x; 1.2056x over previous
#include <cuda_runtime.h>
#include <cstdint>
#include <cstddef>

namespace {

constexpr int kB  = 4;
constexpr int kH  = 8;
constexpr int kL  = 2048;
constexpr int kR  = 8;
constexpr int kDV = 128;

constexpr int TM = 64;           // rows per CTA
constexpr int KT = 32;           // K-tile
constexpr int NT = 256;          // threads
constexpr int NTILES = kL / KT;  // 64

constexpr int PSTRIDE = 36;      // p row stride (u32): ldmatrix rows hit distinct 16B groups
constexpr int VSTRIDE = 136;     // v row stride (u32): B-frag conflict-free
constexpr float kLog2e = 1.44269504088896340736f;

typedef unsigned long long ull;

__device__ __forceinline__ ull dup2(float x) {
    ull r; asm("mov.b64 %0, {%1,%1};" : "=l"(r) : "f"(x)); return r;
}
__device__ __forceinline__ void unpack2(ull v, float& lo, float& hi) {
    asm("mov.b64 {%0,%1}, %2;" : "=f"(lo), "=f"(hi) : "l"(v));
}
__device__ __forceinline__ ull fma2(ull a, ull b, ull c) {
    ull d; asm("fma.rn.f32x2 %0, %1, %2, %3;" : "=l"(d) : "l"(a), "l"(b), "l"(c));
    return d;
}
__device__ __forceinline__ uint32_t f2tf32(float x) {
    uint32_t r; asm("cvt.rna.tf32.f32 %0, %1;" : "=r"(r) : "f"(x)); return r;
}
__device__ __forceinline__ float ex2(float x) {
    float r; asm("ex2.approx.f32 %0, %1;" : "=f"(r) : "f"(x)); return r;
}
__device__ __forceinline__ void mma_tf32(float d[4], const uint32_t a[4],
                                         uint32_t b0, uint32_t b1) {
    asm volatile(
        "mma.sync.aligned.m16n8k8.row.col.f32.tf32.tf32.f32 "
        "{%0,%1,%2,%3}, {%4,%5,%6,%7}, {%8,%9}, {%0,%1,%2,%3};"
        : "+f"(d[0]), "+f"(d[1]), "+f"(d[2]), "+f"(d[3])
        : "r"(a[0]), "r"(a[1]), "r"(a[2]), "r"(a[3]), "r"(b0), "r"(b1));
}
__device__ __forceinline__ void ldmatrix_x4(uint32_t a[4], uint32_t addr) {
    asm volatile(
        "ldmatrix.sync.aligned.m8n8.x4.shared.b16 {%0,%1,%2,%3}, [%4];"
        : "=r"(a[0]), "=r"(a[1]), "=r"(a[2]), "=r"(a[3]) : "r"(addr));
}
__device__ __forceinline__ uint32_t smem_u32(const void* p) {
    uint32_t a;
    asm("{ .reg .u64 t; cvta.to.shared.u64 t, %1; cvt.u32.u64 %0, t; }"
        : "=r"(a) : "l"(p));
    return a;
}
__device__ __forceinline__ void cp16(uint32_t saddr, const void* g) {
    asm volatile("cp.async.ca.shared.global [%0], [%1], 16;"
                 :: "r"(saddr), "l"(g) : "memory");
}
__device__ __forceinline__ void cp_commit() {
    asm volatile("cp.async.commit_group;" ::: "memory");
}
__device__ __forceinline__ void cp_wait1() {
    asm volatile("cp.async.wait_group 1;" ::: "memory");
}

struct __align__(16) SmemLayout {
    uint32_t p[2][TM][PSTRIDE];    // 18.4 KB (tf32 E tiles, double buffered)
    uint32_t v[3][KT][VSTRIDE];    // 52.2 KB (raw f32 v tiles, cp.async ring)
    float    a2t[2][kR][KT];       // 2 KB   (streamed a2 K-tiles)
    float    inv[TM];              // 256 B
};
// ~73 KB -> 2 CTAs/SM

__global__ void __launch_bounds__(NT, 2)
fra_kernel(const float* __restrict__ gv,
           const float* __restrict__ ga1,
           const float* __restrict__ ga2,
           const int*   __restrict__ gmask,
           float* __restrict__ gout,
           float* __restrict__ gattn)
{
    extern __shared__ char smem_raw[];
    SmemLayout& S = *reinterpret_cast<SmemLayout*>(smem_raw);

    const int h    = blockIdx.x;   // heads fastest: 8 heads share mask tile in L2
    const int tile = blockIdx.y;
    const int b    = blockIdx.z;
    const int bh   = b * kH + h;
    const int i0g  = tile * TM;
    const int t    = threadIdx.x;
    const int w    = t >> 5;
    const int l    = t & 31;

    const float* a2base = ga2 + (size_t)bh * kR * kL;
    const float* a1base = ga1 + ((size_t)bh * kL + i0g) * kR;
    const float* vbase  = gv  + (size_t)bh * kL * kDV;
    const int*   mbase  = gmask + ((size_t)b * kL + i0g) * kL;
    float* attnbase = gattn + ((size_t)bh * kL + i0g) * kL;
    float* outbase  = gout  + ((size_t)bh * kL + i0g) * kDV;

    // score mapping: rows 2*rp+i (i=0,1), cols cg*4 within K-tile
    const int rp = t >> 3;   // 0..31
    const int cg = t & 7;    // 0..7

    // a1 (pre-scaled by log2e for ex2) for this thread's 2 rows
    float a1r[2][kR];
    #pragma unroll
    for (int i = 0; i < 2; ++i) {
        const float4* src = (const float4*)(a1base + (size_t)(rp * 2 + i) * kR);
        float4 q0 = src[0], q1 = src[1];
        a1r[i][0] = q0.x * kLog2e; a1r[i][1] = q0.y * kLog2e;
        a1r[i][2] = q0.z * kLog2e; a1r[i][3] = q0.w * kLog2e;
        a1r[i][4] = q1.x * kLog2e; a1r[i][5] = q1.y * kLog2e;
        a1r[i][6] = q1.z * kLog2e; a1r[i][7] = q1.w * kLog2e;
    }

    // GEMM warp grid 2x4 (wm x wn); warp tile 32 rows x 32 cols
    const int wm  = w >> 2;
    const int wn  = w & 3;
    const int qid = l >> 2;
    const int tig = l & 3;

    // ldmatrix A lane address
    const int lrow = 32 * wm + ((l >> 3) & 1) * 8 + (l & 7);
    const int lcol = ((l >> 4) & 1) * 4;
    uint32_t paddr[2];
    paddr[0] = smem_u32(&S.p[0][lrow][lcol]);
    paddr[1] = smem_u32(&S.p[1][lrow][lcol]);

    float acc[2][4][4];
    #pragma unroll
    for (int mt = 0; mt < 2; ++mt)
        #pragma unroll
        for (int nt = 0; nt < 4; ++nt)
            #pragma unroll
            for (int e = 0; e < 4; ++e) acc[mt][nt][e] = 0.f;

    float rs[2] = {0.f, 0.f};

    // ---- cp.async v addressing ----
    const uint32_t vs_base = smem_u32(&S.v[0][0][0]);
    uint32_t voff[4];
    #pragma unroll
    for (int k = 0; k < 4; ++k)
        voff[k] = (uint32_t)(((w + 8 * k) * VSTRIDE + 4 * l) * 4);
    const float* vg[4];
    #pragma unroll
    for (int k = 0; k < 4; ++k)
        vg[k] = vbase + (size_t)(w + 8 * k) * kDV + 4 * l;
    constexpr uint32_t VSLOT = KT * VSTRIDE * 4;
    constexpr size_t   VGT   = (size_t)KT * kDV;

    const int ar = t >> 3;
    const int ac = t & 7;

    int4 mq_buf[2][2];

    // =========================== prologue + peeled jt = 0 ===========================
    {
        // v tile 0 -> slot 0
        #pragma unroll
        for (int k = 0; k < 4; ++k) cp16(vs_base + voff[k], vg[k]);
        cp_commit();

        if (t < 64)
            *(float4*)&S.a2t[0][ar][ac * 4] =
                *(const float4*)(a2base + (size_t)ar * kL + ac * 4);

        #pragma unroll
        for (int i = 0; i < 2; ++i) {
            mq_buf[0][i] = *(const int4*)(mbase + (size_t)(rp * 2 + i) * kL + cg * 4);
            mq_buf[1][i] = *(const int4*)(mbase + (size_t)(rp * 2 + i) * kL + KT + cg * 4);
        }
        __syncthreads();   // a2t[0] visible

        // v tile 1 -> slot 1
        {
            const uint32_t sb = vs_base + VSLOT;
            #pragma unroll
            for (int k = 0; k < 4; ++k) cp16(sb + voff[k], vg[k] + VGT);
            cp_commit();
        }
        float4 a2n;
        if (t < 64)
            a2n = *(const float4*)(a2base + (size_t)ar * kL + KT + ac * 4);

        // scores tile 0
        ull sac[2][2];
        sac[0][0] = 0ULL; sac[0][1] = 0ULL;
        sac[1][0] = 0ULL; sac[1][1] = 0ULL;
        #pragma unroll
        for (int r = 0; r < kR; ++r) {
            ulonglong2 q = *(const ulonglong2*)&S.a2t[0][r][cg * 4];
            #pragma unroll
            for (int i = 0; i < 2; ++i) {
                ull ad = dup2(a1r[i][r]);
                sac[i][0] = fma2(ad, q.x, sac[i][0]);
                sac[i][1] = fma2(ad, q.y, sac[i][1]);
            }
        }
        #pragma unroll
        for (int i = 0; i < 2; ++i) {
            const int row = rp * 2 + i;
            const int4 m = mq_buf[0][i];
            float e0, e1, e2, e3;
            unpack2(sac[i][0], e0, e1);
            unpack2(sac[i][1], e2, e3);
            float4 e;
            e.x = m.x ? ex2(e0) : 0.f;
            e.y = m.y ? ex2(e1) : 0.f;
            e.z = m.z ? ex2(e2) : 0.f;
            e.w = m.w ? ex2(e3) : 0.f;
            rs[i] += (e.x + e.y) + (e.z + e.w);
            *(float4*)(attnbase + (size_t)row * kL + cg * 4) = e;
            uint4 u;
            u.x = f2tf32(e.x); u.y = f2tf32(e.y);
            u.z = f2tf32(e.z); u.w = f2tf32(e.w);
            *(uint4*)&S.p[0][row][cg * 4] = u;
        }
        // mask tile 2 -> slot 0
        #pragma unroll
        for (int i = 0; i < 2; ++i)
            mq_buf[0][i] = *(const int4*)(mbase + (size_t)(rp * 2 + i) * kL + 2 * KT + cg * 4);
        if (t < 64)
            *(float4*)&S.a2t[1][ar][ac * 4] = a2n;

        cp_wait1();        // v tile 0 resident
        __syncthreads();   // publish p[0]/a2t[1]/v(0)
    }

    // ================= main loop jt = 1..63: score(jt) + MMA(jt-1) same epoch =================
    // slot(k) = k % 3: sprev = (jt-1)%3, snxt = (jt+1)%3
    int sprev = 0, snxt = 2;
    #pragma unroll 2
    for (int jt = 1; jt < NTILES; ++jt) {
        const int buf = jt & 1;
        const int j0  = jt * KT;

        // ---- issue cp.async for v tile jt+1 into slot snxt ----
        {
            const size_t goff = (jt + 1 < NTILES) ? (size_t)(jt + 1) * VGT : 0;
            const uint32_t sb = vs_base + (uint32_t)snxt * VSLOT;
            #pragma unroll
            for (int k = 0; k < 4; ++k) cp16(sb + voff[k], vg[k] + goff);
            cp_commit();
        }

        // ---- prefetch next a2 tile ----
        float4 a2n;
        const int jn = (jt + 1 < NTILES) ? j0 + KT : 0;
        if (t < 64)
            a2n = *(const float4*)(a2base + (size_t)ar * kL + jn + ac * 4);

        // ---- scores(jt): LDS a2t[buf] + fma2 ----
        ull sac[2][2];
        sac[0][0] = 0ULL; sac[0][1] = 0ULL;
        sac[1][0] = 0ULL; sac[1][1] = 0ULL;
        #pragma unroll
        for (int r = 0; r < kR; ++r) {
            ulonglong2 q = *(const ulonglong2*)&S.a2t[buf][r][cg * 4];
            #pragma unroll
            for (int i = 0; i < 2; ++i) {
                ull ad = dup2(a1r[i][r]);
                sac[i][0] = fma2(ad, q.x, sac[i][0]);
                sac[i][1] = fma2(ad, q.y, sac[i][1]);
            }
        }

        // ---- MMA(jt-1): p[buf^1], v slot sprev — same epoch, interleaves with above ----
        {
            const uint32_t* vt = &S.v[sprev][0][0];
            const uint32_t ab = paddr[buf ^ 1];
            #pragma unroll
            for (int s = 0; s < 4; ++s) {
                uint32_t a[2][4];
                ldmatrix_x4(a[0], ab + (uint32_t)(s * 32));
                ldmatrix_x4(a[1], ab + (uint32_t)(16 * PSTRIDE * 4 + s * 32));
                #pragma unroll
                for (int nt = 0; nt < 4; ++nt) {
                    const int n = 32 * wn + 8 * nt + qid;
                    uint32_t b0 = vt[(size_t)(8 * s + tig) * VSTRIDE + n];
                    uint32_t b1 = vt[(size_t)(8 * s + 4 + tig) * VSTRIDE + n];
                    mma_tf32(acc[0][nt], a[0], b0, b1);
                    mma_tf32(acc[1][nt], a[1], b0, b1);
                }
            }
        }

        // ---- e = mask*exp2(s): attn STG, rowsum, p STS (tf32) ----
        #pragma unroll
        for (int i = 0; i < 2; ++i) {
            const int row = rp * 2 + i;
            const int4 m = mq_buf[buf][i];
            float e0, e1, e2, e3;
            unpack2(sac[i][0], e0, e1);
            unpack2(sac[i][1], e2, e3);
            float4 e;
            e.x = m.x ? ex2(e0) : 0.f;
            e.y = m.y ? ex2(e1) : 0.f;
            e.z = m.z ? ex2(e2) : 0.f;
            e.w = m.w ? ex2(e3) : 0.f;
            rs[i] += (e.x + e.y) + (e.z + e.w);
            *(float4*)(attnbase + (size_t)row * kL + j0 + cg * 4) = e;
            uint4 u;
            u.x = f2tf32(e.x); u.y = f2tf32(e.y);
            u.z = f2tf32(e.z); u.w = f2tf32(e.w);
            *(uint4*)&S.p[buf][row][cg * 4] = u;
        }

        // ---- mask prefetch 2 tiles ahead ----
        {
            const int jm = (jt + 2 < NTILES) ? (jt + 2) * KT : 0;
            #pragma unroll
            for (int i = 0; i < 2; ++i)
                mq_buf[buf][i] =
                    *(const int4*)(mbase + (size_t)(rp * 2 + i) * kL + jm + cg * 4);
        }

        // ---- stage next a2 tile ----
        if (t < 64)
            *(float4*)&S.a2t[buf ^ 1][ar][ac * 4] = a2n;

        cp_wait1();        // v tile jt resident (only jt+1 pending)
        __syncthreads();   // publish p[buf]/a2t[buf^1]/v(jt)

        sprev = (sprev == 2) ? 0 : sprev + 1;
        snxt  = (snxt  == 2) ? 0 : snxt  + 1;
    }

    // ---- drain: MMA(63): p[1], v slot 63%3 = 0 ----
    {
        const uint32_t* vt = &S.v[sprev][0][0];
        const uint32_t ab = paddr[1];
        #pragma unroll
        for (int s = 0; s < 4; ++s) {
            uint32_t a[2][4];
            ldmatrix_x4(a[0], ab + (uint32_t)(s * 32));
            ldmatrix_x4(a[1], ab + (uint32_t)(16 * PSTRIDE * 4 + s * 32));
            #pragma unroll
            for (int nt = 0; nt < 4; ++nt) {
                const int n = 32 * wn + 8 * nt + qid;
                uint32_t b0 = vt[(size_t)(8 * s + tig) * VSTRIDE + n];
                uint32_t b1 = vt[(size_t)(8 * s + 4 + tig) * VSTRIDE + n];
                mma_tf32(acc[0][nt], a[0], b0, b1);
                mma_tf32(acc[1][nt], a[1], b0, b1);
            }
        }
    }

    // ---- rowsum reduce over 8 cg lanes (warp-local) ----
    float invr[2];
    #pragma unroll
    for (int i = 0; i < 2; ++i) {
        float r = rs[i];
        r += __shfl_xor_sync(0xffffffffu, r, 1);
        r += __shfl_xor_sync(0xffffffffu, r, 2);
        r += __shfl_xor_sync(0xffffffffu, r, 4);
        invr[i] = 1.0f / r;
        if (cg == 0) S.inv[rp * 2 + i] = invr[i];
    }
    __syncthreads();

    // ---- out epilogue: scale accumulators by row inv ----
    #pragma unroll
    for (int mt = 0; mt < 2; ++mt) {
        const int row0 = 32 * wm + 16 * mt + qid;
        const float ivlo = S.inv[row0];
        const float ivhi = S.inv[row0 + 8];
        #pragma unroll
        for (int nt = 0; nt < 4; ++nt) {
            const int col = 32 * wn + 8 * nt + 2 * tig;
            float2 lo; lo.x = acc[mt][nt][0] * ivlo; lo.y = acc[mt][nt][1] * ivlo;
            float2 hi; hi.x = acc[mt][nt][2] * ivhi; hi.y = acc[mt][nt][3] * ivhi;
            *(float2*)(outbase + (size_t)row0 * kDV + col)       = lo;
            *(float2*)(outbase + (size_t)(row0 + 8) * kDV + col) = hi;
        }
    }

    // ---- attn rescale: each thread rescales exactly the float4s it wrote ----
    #pragma unroll
    for (int i = 0; i < 2; ++i) {
        float* aprow = attnbase + (size_t)(rp * 2 + i) * kL + cg * 4;
        const float iv = invr[i];
        #pragma unroll 8
        for (int jt = 0; jt < NTILES; ++jt) {
            float4 e = *(const float4*)(aprow + jt * KT);
            e.x *= iv; e.y *= iv; e.z *= iv; e.w *= iv;
            *(float4*)(aprow + jt * KT) = e;
        }
    }
}

} // namespace

extern "C" void kernel_launch(void* const* d_in, const int* in_sizes, int n_in,
                              void* d_out, int out_size) {
    const float* v    = (const float*)d_in[0];
    const float* a1   = (const float*)d_in[1];
    const float* a2   = (const float*)d_in[2];
    const int*   mask = (const int*)d_in[3];

    float* out  = (float*)d_out;
    float* attn = out + (size_t)kB * kH * kL * kDV;

    const int smem = (int)sizeof(SmemLayout);
    cudaFuncSetAttribute(fra_kernel, cudaFuncAttributeMaxDynamicSharedMemorySize, smem);

    dim3 grid(kH, kL / TM, kB);   // heads fastest -> mask tile L2 reuse across 8 heads
    fra_kernel<<<grid, NT, smem>>>(v, a1, a2, mask, out, attn);
}